// round 15
// baseline (speedup 1.0000x reference)
#include <cuda_runtime.h>
#include <cstdint>

// Problem dims (fixed by reference)
#define BB 256
#define TT 1024
#define DD 64
#define HH 128
#define NB 8      // batches per scan CTA (MMA N dimension)

typedef unsigned long long ull;

static constexpr size_t BT  = (size_t)BB * TT;        // 262144
static constexpr size_t BTH = (size_t)BB * TT * HH;   // 33554432

// Interleaved scratch: (gate_x_K, tanh(gate_x_z)) per (b,t,h). No cudaMalloc.
// Padded 4 rows so scan prefetch (distance 2) is unconditional.
__device__ float2 g_gz[BTH + 4 * HH];

// ---- helpers ----
__device__ __forceinline__ float tanh_hw(float x) {
    float r;
    asm("tanh.approx.f32 %0, %1;" : "=f"(r) : "f"(x));
    return r;
}
__device__ __forceinline__ float sigmoid_hw(float x) {
    return fmaf(0.5f, tanh_hw(0.5f * x), 0.5f);
}
__device__ __forceinline__ uint32_t to_tf32(float x) {
    uint32_t u;
    asm("cvt.rn.tf32.f32 %0, %1;" : "=r"(u) : "f"(x));
    return u;
}

// m16n8k8 tf32 MMA, scalar-ref form (no arrays -> no local-mem risk).
// Fragment maps (g = lane>>2, tig = lane&3):
//   A (row-major): a0=(g,tig) a1=(g+8,tig) a2=(g,tig+4) a3=(g+8,tig+4)
//   B (col-major): b0=(k=tig, n=g) b1=(k=tig+4, n=g)
//   C: c0=(g,2tig) c1=(g,2tig+1) c2=(g+8,2tig) c3=(g+8,2tig+1)
__device__ __forceinline__ void mma4(float& c0, float& c1, float& c2, float& c3,
                                     uint32_t a0, uint32_t a1, uint32_t a2, uint32_t a3,
                                     uint32_t b0, uint32_t b1) {
    asm volatile(
        "mma.sync.aligned.m16n8k8.row.col.f32.tf32.tf32.f32 "
        "{%0,%1,%2,%3}, {%4,%5,%6,%7}, {%8,%9}, {%0,%1,%2,%3};"
        : "+f"(c0), "+f"(c1), "+f"(c2), "+f"(c3)
        : "r"(a0), "r"(a1), "r"(a2), "r"(a3), "r"(b0), "r"(b1));
}

// ---------------------------------------------------------------------------
// Kernel 1: tensor-core input projections (r14 verbatim; ~107us).
// ---------------------------------------------------------------------------
#define XS_OFF  0
#define WK_OFF  (64 * 68)
#define WZ_OFF  (WK_OFF + 128 * 68)
#define BK_OFF  (WZ_OFF + 128 * 68)
#define BZ_OFF  (BK_OFF + 128)
#define PROJ_SMEM_FLOATS (BZ_OFF + 128)

__global__ void __launch_bounds__(128, 2)
proj_kernel(const float* __restrict__ x,
            const float* __restrict__ WxK, const float* __restrict__ bxK,
            const float* __restrict__ Wxz, const float* __restrict__ bxz)
{
    extern __shared__ float sm[];
    float* xs  = sm + XS_OFF;
    float* wks = sm + WK_OFF;
    float* wzs = sm + WZ_OFF;
    float* bks = sm + BK_OFF;
    float* bzs = sm + BZ_OFF;

    const int tid  = threadIdx.x;
    const int w    = tid >> 5;
    const int lane = tid & 31;
    const int g    = lane >> 2;
    const int tig  = lane & 3;
    const size_t row0 = (size_t)blockIdx.x * 64;

    {
        const float4* xg = (const float4*)(x + row0 * DD);
#pragma unroll
        for (int it = 0; it < 8; it++) {
            int idx = tid + 128 * it;
            int r = idx >> 4, c = (idx & 15) << 2;
            *(float4*)(xs + r * 68 + c) = xg[idx];
        }
    }
    {
        const float4* wk4 = (const float4*)WxK;
        const float4* wz4 = (const float4*)Wxz;
#pragma unroll
        for (int it = 0; it < 16; it++) {
            int idx = tid + 128 * it;
            int r = idx >> 4, c = (idx & 15) << 2;
            float4 a = wk4[idx], b = wz4[idx];
            float4 at, bt;
            at.x = __uint_as_float(to_tf32(a.x));
            at.y = __uint_as_float(to_tf32(a.y));
            at.z = __uint_as_float(to_tf32(a.z));
            at.w = __uint_as_float(to_tf32(a.w));
            bt.x = __uint_as_float(to_tf32(b.x));
            bt.y = __uint_as_float(to_tf32(b.y));
            bt.z = __uint_as_float(to_tf32(b.z));
            bt.w = __uint_as_float(to_tf32(b.w));
            *(float4*)(wks + r * 68 + c) = at;
            *(float4*)(wzs + r * 68 + c) = bt;
        }
    }
    bks[tid & 127] = bxK[tid & 127];
    bzs[tid & 127] = bxz[tid & 127];
    __syncthreads();

    uint32_t A[8][4];
    const int rA0 = 16 * w + g, rA1 = rA0 + 8;
#pragma unroll
    for (int kc = 0; kc < 8; kc++) {
        int cb = 8 * kc + tig;
        A[kc][0] = to_tf32(xs[rA0 * 68 + cb]);
        A[kc][1] = to_tf32(xs[rA1 * 68 + cb]);
        A[kc][2] = to_tf32(xs[rA0 * 68 + cb + 4]);
        A[kc][3] = to_tf32(xs[rA1 * 68 + cb + 4]);
    }

    float4* ogz = (float4*)g_gz;
    const size_t o0 = (row0 + rA0) * 64;
    const size_t o1 = (row0 + rA1) * 64;

#pragma unroll 4
    for (int nt = 0; nt < 16; nt++) {
        const float* wkr = wks + (8 * nt + g) * 68 + tig;
        const float* wzr = wzs + (8 * nt + g) * 68 + tig;
        uint32_t BK0[8], BK1[8], BZ0[8], BZ1[8];
#pragma unroll
        for (int kc = 0; kc < 8; kc++) {
            BK0[kc] = __float_as_uint(wkr[8 * kc]);
            BK1[kc] = __float_as_uint(wkr[8 * kc + 4]);
            BZ0[kc] = __float_as_uint(wzr[8 * kc]);
            BZ1[kc] = __float_as_uint(wzr[8 * kc + 4]);
        }
        float cK[4] = {0, 0, 0, 0}, cz[4] = {0, 0, 0, 0};
#pragma unroll
        for (int kc = 0; kc < 8; kc++) {
            mma4(cK[0], cK[1], cK[2], cK[3],
                 A[kc][0], A[kc][1], A[kc][2], A[kc][3], BK0[kc], BK1[kc]);
            mma4(cz[0], cz[1], cz[2], cz[3],
                 A[kc][0], A[kc][1], A[kc][2], A[kc][3], BZ0[kc], BZ1[kc]);
        }
        const int h0 = 8 * nt + 2 * tig;
        const float bk0 = bks[h0], bk1 = bks[h0 + 1];
        const float bz0 = bzs[h0], bz1 = bzs[h0 + 1];

        float4 v0, v1;
        v0.x = cK[0] + bk0;  v0.y = tanh_hw(cz[0] + bz0);
        v0.z = cK[1] + bk1;  v0.w = tanh_hw(cz[1] + bz1);
        v1.x = cK[2] + bk0;  v1.y = tanh_hw(cz[2] + bz0);
        v1.z = cK[3] + bk1;  v1.w = tanh_hw(cz[3] + bz1);
        ogz[o0 + 4 * nt + tig] = v0;
        ogz[o1 + 4 * nt + tig] = v1;
    }
}

// ---------------------------------------------------------------------------
// Kernel 2: tensor-core scan, SPILL-FREE rewrite of r12.
// One CTA (256 thr = 8 warps) x NB=8 batches; grid = 32.
// C[128x8] = W[128x128] @ H[128x8] per step, A register-resident.
// ALL per-thread state is named scalars (no indexable arrays):
//   - B fragments loaded in two 8-chunk waves (16 live regs),
//   - C = 4 float4 chains,
//   - 12 pointers + 4 h + 8 gate float2s as scalars.
// ---------------------------------------------------------------------------
__global__ void __launch_bounds__(256, 1)
scan_kernel(const float* __restrict__ WhK, const float* __restrict__ bhK,
            float* __restrict__ out, int dup)
{
    __shared__ float hs[2][NB][132];   // bank(n*132+k)=(4n+k)%32: conflict-free

    const int tid  = threadIdx.x;
    const int w    = tid >> 5;
    const int lane = tid & 31;
    const int g    = lane >> 2;
    const int tig  = lane & 3;
    const int b0blk = blockIdx.x * NB;

    // A fragments: rows (16w+g, +8), 16 k-chunks (constant-indexed, promoted).
    uint32_t A[16][4];
    const int i0 = 16 * w + g;
    const int i1 = i0 + 8;
#pragma unroll
    for (int kc = 0; kc < 16; kc++) {
        int kb = 8 * kc + tig;
        A[kc][0] = to_tf32(WhK[i0 * HH + kb]);
        A[kc][1] = to_tf32(WhK[i1 * HH + kb]);
        A[kc][2] = to_tf32(WhK[i0 * HH + kb + 4]);
        A[kc][3] = to_tf32(WhK[i1 * HH + kb + 4]);
    }
    const float bh0 = bhK[i0];
    const float bh1 = bhK[i1];

    const int n0 = 2 * tig, n1 = n0 + 1;

    // Named-scalar pointers for the 4 (i,n) streams.
    const size_t base0 = ((size_t)(b0blk + n0) * TT) * HH + i0;   // (i0,n0)
    const size_t base1 = ((size_t)(b0blk + n1) * TT) * HH + i0;   // (i0,n1)
    const size_t base2 = ((size_t)(b0blk + n0) * TT) * HH + i1;   // (i1,n0)
    const size_t base3 = ((size_t)(b0blk + n1) * TT) * HH + i1;   // (i1,n1)

    const float2* gp0 = g_gz + base0;
    const float2* gp1 = g_gz + base1;
    const float2* gp2 = g_gz + base2;
    const float2* gp3 = g_gz + base3;
    float* op0 = out + base0;  float* oq0 = op0 + BTH;
    float* op1 = out + base1;  float* oq1 = op1 + BTH;
    float* op2 = out + base2;  float* oq2 = op2 + BTH;
    float* op3 = out + base3;  float* oq3 = op3 + BTH;

    float h0 = 0.f, h1 = 0.f, h2 = 0.f, h3 = 0.f;
    float2 ga0 = gp0[0], ga1 = gp1[0], ga2 = gp2[0], ga3 = gp3[0];
    float2 gb0 = gp0[HH], gb1 = gp1[HH], gb2 = gp2[HH], gb3 = gp3[HH];
    gp0 += 2 * HH; gp1 += 2 * HH; gp2 += 2 * HH; gp3 += 2 * HH;

    for (int idx = tid; idx < NB * 132; idx += 256)
        (&hs[0][0][0])[idx] = 0.0f;
    __syncthreads();

    int cur = 0;
    for (int t = 0; t < TT; t++) {
        const float* hb = &hs[cur][0][0] + g * 132 + tig;

        float4 cA = {0,0,0,0}, cB = {0,0,0,0}, cC = {0,0,0,0}, cD = {0,0,0,0};

        // ---- wave 0: chunks 0..7 (16 B regs live) ----
        {
            uint32_t p0a = __float_as_uint(hb[0]),   p0b = __float_as_uint(hb[4]);
            uint32_t p1a = __float_as_uint(hb[8]),   p1b = __float_as_uint(hb[12]);
            uint32_t p2a = __float_as_uint(hb[16]),  p2b = __float_as_uint(hb[20]);
            uint32_t p3a = __float_as_uint(hb[24]),  p3b = __float_as_uint(hb[28]);
            uint32_t p4a = __float_as_uint(hb[32]),  p4b = __float_as_uint(hb[36]);
            uint32_t p5a = __float_as_uint(hb[40]),  p5b = __float_as_uint(hb[44]);
            uint32_t p6a = __float_as_uint(hb[48]),  p6b = __float_as_uint(hb[52]);
            uint32_t p7a = __float_as_uint(hb[56]),  p7b = __float_as_uint(hb[60]);
            mma4(cA.x, cA.y, cA.z, cA.w, A[0][0], A[0][1], A[0][2], A[0][3], p0a, p0b);
            mma4(cB.x, cB.y, cB.z, cB.w, A[1][0], A[1][1], A[1][2], A[1][3], p1a, p1b);
            mma4(cC.x, cC.y, cC.z, cC.w, A[2][0], A[2][1], A[2][2], A[2][3], p2a, p2b);
            mma4(cD.x, cD.y, cD.z, cD.w, A[3][0], A[3][1], A[3][2], A[3][3], p3a, p3b);
            mma4(cA.x, cA.y, cA.z, cA.w, A[4][0], A[4][1], A[4][2], A[4][3], p4a, p4b);
            mma4(cB.x, cB.y, cB.z, cB.w, A[5][0], A[5][1], A[5][2], A[5][3], p5a, p5b);
            mma4(cC.x, cC.y, cC.z, cC.w, A[6][0], A[6][1], A[6][2], A[6][3], p6a, p6b);
            mma4(cD.x, cD.y, cD.z, cD.w, A[7][0], A[7][1], A[7][2], A[7][3], p7a, p7b);
        }
        // ---- wave 1: chunks 8..15 ----
        {
            uint32_t p0a = __float_as_uint(hb[64]),  p0b = __float_as_uint(hb[68]);
            uint32_t p1a = __float_as_uint(hb[72]),  p1b = __float_as_uint(hb[76]);
            uint32_t p2a = __float_as_uint(hb[80]),  p2b = __float_as_uint(hb[84]);
            uint32_t p3a = __float_as_uint(hb[88]),  p3b = __float_as_uint(hb[92]);
            uint32_t p4a = __float_as_uint(hb[96]),  p4b = __float_as_uint(hb[100]);
            uint32_t p5a = __float_as_uint(hb[104]), p5b = __float_as_uint(hb[108]);
            uint32_t p6a = __float_as_uint(hb[112]), p6b = __float_as_uint(hb[116]);
            uint32_t p7a = __float_as_uint(hb[120]), p7b = __float_as_uint(hb[124]);
            mma4(cA.x, cA.y, cA.z, cA.w, A[8][0],  A[8][1],  A[8][2],  A[8][3],  p0a, p0b);
            mma4(cB.x, cB.y, cB.z, cB.w, A[9][0],  A[9][1],  A[9][2],  A[9][3],  p1a, p1b);
            mma4(cC.x, cC.y, cC.z, cC.w, A[10][0], A[10][1], A[10][2], A[10][3], p2a, p2b);
            mma4(cD.x, cD.y, cD.z, cD.w, A[11][0], A[11][1], A[11][2], A[11][3], p3a, p3b);
            mma4(cA.x, cA.y, cA.z, cA.w, A[12][0], A[12][1], A[12][2], A[12][3], p4a, p4b);
            mma4(cB.x, cB.y, cB.z, cB.w, A[13][0], A[13][1], A[13][2], A[13][3], p5a, p5b);
            mma4(cC.x, cC.y, cC.z, cC.w, A[14][0], A[14][1], A[14][2], A[14][3], p6a, p6b);
            mma4(cD.x, cD.y, cD.z, cD.w, A[15][0], A[15][1], A[15][2], A[15][3], p7a, p7b);
        }

        // reduce 4 chains; c-element j of thread -> output j
        float s0 = ((cA.x + cB.x) + (cC.x + cD.x)) + bh0;
        float s1 = ((cA.y + cB.y) + (cC.y + cD.y)) + bh0;
        float s2 = ((cA.z + cB.z) + (cC.z + cD.z)) + bh1;
        float s3 = ((cA.w + cB.w) + (cC.w + cD.w)) + bh1;

        // activations (pipelined MUFUs)
        float k0 = sigmoid_hw(ga0.x + s0);
        float k1 = sigmoid_hw(ga1.x + s1);
        float k2 = sigmoid_hw(ga2.x + s2);
        float k3 = sigmoid_hw(ga3.x + s3);
        h0 = tanh_hw(fmaf(k0, ga0.y - h0, h0));
        h1 = tanh_hw(fmaf(k1, ga1.y - h1, h1));
        h2 = tanh_hw(fmaf(k2, ga2.y - h2, h2));
        h3 = tanh_hw(fmaf(k3, ga3.y - h3, h3));

        // rotate gate prefetch (unconditional; padded scratch)
        ga0 = gb0; ga1 = gb1; ga2 = gb2; ga3 = gb3;
        gb0 = *gp0; gb1 = *gp1; gb2 = *gp2; gb3 = *gp3;
        gp0 += HH; gp1 += HH; gp2 += HH; gp3 += HH;

        op0[0] = h0; op1[0] = h1; op2[0] = h2; op3[0] = h3;
        if (dup) { oq0[0] = h0; oq1[0] = h1; oq2[0] = h2; oq3[0] = h3; }
        op0 += HH; op1 += HH; op2 += HH; op3 += HH;
        oq0 += HH; oq1 += HH; oq2 += HH; oq3 += HH;

        // stage tf32-rounded h for next step (conflict-free)
        int nxt = cur ^ 1;
        hs[nxt][n0][i0] = __uint_as_float(to_tf32(h0));
        hs[nxt][n1][i0] = __uint_as_float(to_tf32(h1));
        hs[nxt][n0][i1] = __uint_as_float(to_tf32(h2));
        hs[nxt][n1][i1] = __uint_as_float(to_tf32(h3));
        __syncthreads();
        cur = nxt;
    }
}

// ---------------------------------------------------------------------------
extern "C" void kernel_launch(void* const* d_in, const int* in_sizes, int n_in,
                              void* d_out, int out_size)
{
    const float* x   = (const float*)d_in[0];
    const float* WxK = (const float*)d_in[1];
    const float* bxK = (const float*)d_in[2];
    const float* Wxz = (const float*)d_in[3];
    const float* bxz = (const float*)d_in[4];
    const float* WhK = (const float*)d_in[5];
    const float* bhK = (const float*)d_in[6];
    float* out = (float*)d_out;

    const int proj_smem = PROJ_SMEM_FLOATS * (int)sizeof(float);   // ~88KB
    static int attr_set = 0;
    if (!attr_set) {
        cudaFuncSetAttribute(proj_kernel,
                             cudaFuncAttributeMaxDynamicSharedMemorySize,
                             proj_smem);
        attr_set = 1;
    }

    proj_kernel<<<(int)(BT / 64), 128, proj_smem>>>(x, WxK, bxK, Wxz, bxz);

    const int dup = ((size_t)out_size >= 2 * BTH) ? 1 : 0;
    scan_kernel<<<BB / NB, 256>>>(WhK, bhK, out, dup);
}

// round 16
// speedup vs baseline: 1.1455x; 1.1455x over previous
#include <cuda_runtime.h>
#include <cstdint>

// Problem dims (fixed by reference)
#define BB 256
#define TT 1024
#define DD 64
#define HH 128

typedef unsigned long long ull;

static constexpr size_t BT  = (size_t)BB * TT;        // 262144
static constexpr size_t BTH = (size_t)BB * TT * HH;   // 33554432

// Interleaved scratch: (gate_x_K, tanh(gate_x_z)) per (b,t,h). No cudaMalloc.
// Padded 4 rows so scan prefetch (distance 2) is unconditional.
__device__ float2 g_gz[BTH + 4 * HH];

// ---- helpers ----
__device__ __forceinline__ void fma2(ull& acc, ull a, ull b) {
    asm("fma.rn.f32x2 %0, %1, %2, %0;" : "+l"(acc) : "l"(a), "l"(b));
}
__device__ __forceinline__ void add2(ull& a, ull b) {
    asm("add.rn.f32x2 %0, %0, %1;" : "+l"(a) : "l"(b));
}
__device__ __forceinline__ float2 unpk(ull v) {
    float2 f;
    asm("mov.b64 {%0, %1}, %2;" : "=f"(f.x), "=f"(f.y) : "l"(v));
    return f;
}
__device__ __forceinline__ float tanh_hw(float x) {
    float r;
    asm("tanh.approx.f32 %0, %1;" : "=f"(r) : "f"(x));
    return r;
}
__device__ __forceinline__ float sigmoid_hw(float x) {
    return fmaf(0.5f, tanh_hw(0.5f * x), 0.5f);
}
__device__ __forceinline__ uint32_t to_tf32(float x) {
    uint32_t u;
    asm("cvt.rn.tf32.f32 %0, %1;" : "=r"(u) : "f"(x));
    return u;
}

// m16n8k8 tf32 MMA (proj kernel only).
__device__ __forceinline__ void mma4(float& c0, float& c1, float& c2, float& c3,
                                     uint32_t a0, uint32_t a1, uint32_t a2, uint32_t a3,
                                     uint32_t b0, uint32_t b1) {
    asm volatile(
        "mma.sync.aligned.m16n8k8.row.col.f32.tf32.tf32.f32 "
        "{%0,%1,%2,%3}, {%4,%5,%6,%7}, {%8,%9}, {%0,%1,%2,%3};"
        : "+f"(c0), "+f"(c1), "+f"(c2), "+f"(c3)
        : "r"(a0), "r"(a1), "r"(a2), "r"(a3), "r"(b0), "r"(b1));
}

// ---------------------------------------------------------------------------
// Kernel 1: tensor-core input projections (r14 verbatim; ~107us).
// ---------------------------------------------------------------------------
#define XS_OFF  0
#define WK_OFF  (64 * 68)
#define WZ_OFF  (WK_OFF + 128 * 68)
#define BK_OFF  (WZ_OFF + 128 * 68)
#define BZ_OFF  (BK_OFF + 128)
#define PROJ_SMEM_FLOATS (BZ_OFF + 128)

__global__ void __launch_bounds__(128, 2)
proj_kernel(const float* __restrict__ x,
            const float* __restrict__ WxK, const float* __restrict__ bxK,
            const float* __restrict__ Wxz, const float* __restrict__ bxz)
{
    extern __shared__ float sm[];
    float* xs  = sm + XS_OFF;
    float* wks = sm + WK_OFF;
    float* wzs = sm + WZ_OFF;
    float* bks = sm + BK_OFF;
    float* bzs = sm + BZ_OFF;

    const int tid  = threadIdx.x;
    const int w    = tid >> 5;
    const int lane = tid & 31;
    const int g    = lane >> 2;
    const int tig  = lane & 3;
    const size_t row0 = (size_t)blockIdx.x * 64;

    {
        const float4* xg = (const float4*)(x + row0 * DD);
#pragma unroll
        for (int it = 0; it < 8; it++) {
            int idx = tid + 128 * it;
            int r = idx >> 4, c = (idx & 15) << 2;
            *(float4*)(xs + r * 68 + c) = xg[idx];
        }
    }
    {
        const float4* wk4 = (const float4*)WxK;
        const float4* wz4 = (const float4*)Wxz;
#pragma unroll
        for (int it = 0; it < 16; it++) {
            int idx = tid + 128 * it;
            int r = idx >> 4, c = (idx & 15) << 2;
            float4 a = wk4[idx], b = wz4[idx];
            float4 at, bt;
            at.x = __uint_as_float(to_tf32(a.x));
            at.y = __uint_as_float(to_tf32(a.y));
            at.z = __uint_as_float(to_tf32(a.z));
            at.w = __uint_as_float(to_tf32(a.w));
            bt.x = __uint_as_float(to_tf32(b.x));
            bt.y = __uint_as_float(to_tf32(b.y));
            bt.z = __uint_as_float(to_tf32(b.z));
            bt.w = __uint_as_float(to_tf32(b.w));
            *(float4*)(wks + r * 68 + c) = at;
            *(float4*)(wzs + r * 68 + c) = bt;
        }
    }
    bks[tid & 127] = bxK[tid & 127];
    bzs[tid & 127] = bxz[tid & 127];
    __syncthreads();

    uint32_t A[8][4];
    const int rA0 = 16 * w + g, rA1 = rA0 + 8;
#pragma unroll
    for (int kc = 0; kc < 8; kc++) {
        int cb = 8 * kc + tig;
        A[kc][0] = to_tf32(xs[rA0 * 68 + cb]);
        A[kc][1] = to_tf32(xs[rA1 * 68 + cb]);
        A[kc][2] = to_tf32(xs[rA0 * 68 + cb + 4]);
        A[kc][3] = to_tf32(xs[rA1 * 68 + cb + 4]);
    }

    float4* ogz = (float4*)g_gz;
    const size_t o0 = (row0 + rA0) * 64;
    const size_t o1 = (row0 + rA1) * 64;

#pragma unroll 4
    for (int nt = 0; nt < 16; nt++) {
        const float* wkr = wks + (8 * nt + g) * 68 + tig;
        const float* wzr = wzs + (8 * nt + g) * 68 + tig;
        uint32_t BK0[8], BK1[8], BZ0[8], BZ1[8];
#pragma unroll
        for (int kc = 0; kc < 8; kc++) {
            BK0[kc] = __float_as_uint(wkr[8 * kc]);
            BK1[kc] = __float_as_uint(wkr[8 * kc + 4]);
            BZ0[kc] = __float_as_uint(wzr[8 * kc]);
            BZ1[kc] = __float_as_uint(wzr[8 * kc + 4]);
        }
        float cK[4] = {0, 0, 0, 0}, cz[4] = {0, 0, 0, 0};
#pragma unroll
        for (int kc = 0; kc < 8; kc++) {
            mma4(cK[0], cK[1], cK[2], cK[3],
                 A[kc][0], A[kc][1], A[kc][2], A[kc][3], BK0[kc], BK1[kc]);
            mma4(cz[0], cz[1], cz[2], cz[3],
                 A[kc][0], A[kc][1], A[kc][2], A[kc][3], BZ0[kc], BZ1[kc]);
        }
        const int h0 = 8 * nt + 2 * tig;
        const float bk0 = bks[h0], bk1 = bks[h0 + 1];
        const float bz0 = bzs[h0], bz1 = bzs[h0 + 1];

        float4 v0, v1;
        v0.x = cK[0] + bk0;  v0.y = tanh_hw(cz[0] + bz0);
        v0.z = cK[1] + bk1;  v0.w = tanh_hw(cz[1] + bz1);
        v1.x = cK[2] + bk0;  v1.y = tanh_hw(cz[2] + bz0);
        v1.z = cK[3] + bk1;  v1.w = tanh_hw(cz[3] + bz1);
        ogz[o0 + 4 * nt + tig] = v0;
        ogz[o1 + 4 * nt + tig] = v1;
    }
}

// ---------------------------------------------------------------------------
// Kernel 2: sequential scan, QUARTER-SPLIT. One CTA (512 thr) per batch,
// grid = 256 -> 2 CTAs/SM (2 independent barrier domains, 8 warps/SMSP).
// Output i = tid>>2 computed by the lane QUAD (q = tid&3):
//   lane q dots h[32q .. 32q+31] (16 ull weights = 32 regs, 8 LDS.128),
//   quad combined with 2 shfl.bfly; all 4 lanes compute the identical
//   activation. Lane q0 stores out + next h; lane q1 stores the dup copy.
// h stage padded to 40 floats per quarter -> the 4 distinct quad addresses
// per LDS.128 hit banks {0,8,16,24}+4m: conflict-free.
// Register budget ~55-60 -> fits 64-reg cap for 1024 thr/SM.
// ---------------------------------------------------------------------------
__global__ void __launch_bounds__(512, 2)
scan_kernel(const float* __restrict__ WhK, const float* __restrict__ bhK,
            float* __restrict__ out, int dup)
{
    __shared__ __align__(16) float hst[2][160];   // h[j] at 40*(j>>5) + (j&31)

    const int tid = threadIdx.x;
    const int i   = tid >> 2;        // output index 0..127
    const int q   = tid & 3;         // quarter 0..3
    const int b   = blockIdx.x;

    // This lane's 32 weights: W_hK[i][32q .. +32) as 16 f32x2.
    ull w[16];
    {
        const ull* wr = (const ull*)(WhK + i * HH + 32 * q);
#pragma unroll
        for (int m = 0; m < 16; m++) w[m] = wr[m];
    }
    const float bh = bhK[i];

    const float2* gp = g_gz + (size_t)b * TT * HH + i;
    // q0 -> main output, q1 -> duplicate copy, q2/q3 -> no store.
    float* outp = out + (size_t)b * TT * HH + i + (q == 1 ? BTH : 0);
    const bool do_store = (q == 0) || (q == 1 && dup);
    const int hidx = 40 * (i >> 5) + (i & 31);   // stage slot for output i

    float h = 0.0f;
    if (tid < 160) hst[0][tid] = 0.0f;

    float2 gz0 = gp[0];
    float2 gz1 = gp[HH];
    gp += 2 * HH;
    __syncthreads();

    int cur = 0;
    for (int t = 0; t < TT; t++) {
        // Quarter-dot: 8 LDS.128 from this quarter's padded block.
        const ulonglong2* hv = (const ulonglong2*)(hst[cur] + 40 * q);
        ull a0 = 0, a1 = 0, a2 = 0, a3 = 0;
#pragma unroll
        for (int m = 0; m < 8; m += 2) {        // 8 ulonglong2 = 32 floats
            ulonglong2 hA = hv[m];
            ulonglong2 hB = hv[m + 1];
            fma2(a0, w[2 * m],     hA.x);
            fma2(a1, w[2 * m + 1], hA.y);
            fma2(a2, w[2 * m + 2], hB.x);
            fma2(a3, w[2 * m + 3], hB.y);
        }
        add2(a0, a2); add2(a1, a3); add2(a0, a1);
        float2 p = unpk(a0);
        float s = p.x + p.y;
        s += __shfl_xor_sync(0xFFFFFFFFu, s, 1);   // combine quad
        s += __shfl_xor_sync(0xFFFFFFFFu, s, 2);
        s += bh;

        // all 4 lanes compute the identical activation
        float kg = sigmoid_hw(gz0.x + s);
        h = tanh_hw(fmaf(kg, gz0.y - h, h));

        // rotate gate prefetch (unconditional; scratch padded)
        gz0 = gz1;
        gz1 = *gp;
        gp += HH;

        if (do_store) outp[0] = h;
        outp += HH;

        cur ^= 1;
        if (q == 0) hst[cur][hidx] = h;
        __syncthreads();
    }
}

// ---------------------------------------------------------------------------
extern "C" void kernel_launch(void* const* d_in, const int* in_sizes, int n_in,
                              void* d_out, int out_size)
{
    const float* x   = (const float*)d_in[0];
    const float* WxK = (const float*)d_in[1];
    const float* bxK = (const float*)d_in[2];
    const float* Wxz = (const float*)d_in[3];
    const float* bxz = (const float*)d_in[4];
    const float* WhK = (const float*)d_in[5];
    const float* bhK = (const float*)d_in[6];
    float* out = (float*)d_out;

    const int proj_smem = PROJ_SMEM_FLOATS * (int)sizeof(float);   // ~88KB
    static int attr_set = 0;
    if (!attr_set) {
        cudaFuncSetAttribute(proj_kernel,
                             cudaFuncAttributeMaxDynamicSharedMemorySize,
                             proj_smem);
        attr_set = 1;
    }

    proj_kernel<<<(int)(BT / 64), 128, proj_smem>>>(x, WxK, bxK, Wxz, bxz);

    const int dup = ((size_t)out_size >= 2 * BTH) ? 1 : 0;
    scan_kernel<<<BB, 512>>>(WhK, bhK, out, dup);
}

// round 17
// speedup vs baseline: 1.4876x; 1.2987x over previous
#include <cuda_runtime.h>
#include <cstdint>

// Problem dims (fixed by reference)
#define BB 256
#define TT 1024
#define DD 64
#define HH 128
#define GRP 2            // batches per scan CTA
#define NCHUNK 16        // 16 chunks of 64 timesteps
#define SCAN_CTAS 128
#define TOTAL_CTAS 148   // <= SM count (148 B300 / 152 GB300): all resident
#define WORK_TEAMS 80    // (TOTAL_CTAS - SCAN_CTAS) * 4

typedef unsigned long long ull;

static constexpr size_t BT  = (size_t)BB * TT;        // 262144
static constexpr size_t BTH = (size_t)BB * TT * HH;   // 33554432

// Interleaved gate scratch: (gate_x_K, tanh(gate_x_z)) per (b,t,h).
// Padded 4 rows so scan prefetch (depth 3) is unconditional.
__device__ float2 g_gz[BTH + 4 * HH];
// Per-chunk completion counters (tiles done out of 256).
__device__ int g_done[NCHUNK];

// ---- helpers ----
__device__ __forceinline__ void fma2(ull& acc, ull a, ull b) {
    asm("fma.rn.f32x2 %0, %1, %2, %0;" : "+l"(acc) : "l"(a), "l"(b));
}
__device__ __forceinline__ void add2(ull& a, ull b) {
    asm("add.rn.f32x2 %0, %0, %1;" : "+l"(a) : "l"(b));
}
__device__ __forceinline__ float2 unpk(ull v) {
    float2 f;
    asm("mov.b64 {%0, %1}, %2;" : "=f"(f.x), "=f"(f.y) : "l"(v));
    return f;
}
__device__ __forceinline__ float tanh_hw(float x) {
    float r;
    asm("tanh.approx.f32 %0, %1;" : "=f"(r) : "f"(x));
    return r;
}
__device__ __forceinline__ float sigmoid_hw(float x) {
    return fmaf(0.5f, tanh_hw(0.5f * x), 0.5f);
}
__device__ __forceinline__ uint32_t to_tf32(float x) {
    uint32_t u;
    asm("cvt.rn.tf32.f32 %0, %1;" : "=r"(u) : "f"(x));
    return u;
}
__device__ __forceinline__ void mma4(float& c0, float& c1, float& c2, float& c3,
                                     uint32_t a0, uint32_t a1, uint32_t a2, uint32_t a3,
                                     uint32_t b0, uint32_t b1) {
    asm volatile(
        "mma.sync.aligned.m16n8k8.row.col.f32.tf32.tf32.f32 "
        "{%0,%1,%2,%3}, {%4,%5,%6,%7}, {%8,%9}, {%0,%1,%2,%3};"
        : "+f"(c0), "+f"(c1), "+f"(c2), "+f"(c3)
        : "r"(a0), "r"(a1), "r"(a2), "r"(a3), "r"(b0), "r"(b1));
}

// Dynamic smem layout (float units) — used by proj-worker CTAs only.
#define WK_OFF  0                         // 128 x 68
#define WZ_OFF  8704                      // 128 x 68
#define XS_OFF  17408                     // 4 teams x (64 x 68)
#define BK_OFF  (XS_OFF + 4 * 4352)       // 34816
#define BZ_OFF  (BK_OFF + 128)            // 34944
#define DYN_FLOATS (BZ_OFF + 128)         // 35072 floats = 140288 B

__global__ void zero_done_kernel() {
    if (threadIdx.x < NCHUNK) g_done[threadIdx.x] = 0;
}

__global__ void __launch_bounds__(512, 1)
fused_kernel(const float* __restrict__ x,
             const float* __restrict__ WxK, const float* __restrict__ bxK,
             const float* __restrict__ Wxz, const float* __restrict__ bxz,
             const float* __restrict__ WhK, const float* __restrict__ bhK,
             float* __restrict__ out, int dup)
{
    extern __shared__ float sm[];
    // Scan h-stage (static, tiny). h[j] at j + 8*(j>=64): halves bank-disjoint.
    __shared__ __align__(16) float hst[2][GRP][144];

    const int tid = threadIdx.x;
    const int bx  = blockIdx.x;

    if (bx >= SCAN_CTAS) {
        // ================= PROJ WORKER CTA =================
        float* wks = sm + WK_OFF;
        float* wzs = sm + WZ_OFF;
        float* bks = sm + BK_OFF;
        float* bzs = sm + BZ_OFF;

        // Stage both W matrices once (tf32-rounded), 512 threads.
        {
            const float4* wk4 = (const float4*)WxK;
            const float4* wz4 = (const float4*)Wxz;
#pragma unroll
            for (int it = 0; it < 4; it++) {
                int idx = tid + 512 * it;             // 2048 float4s
                int r = idx >> 4, c = (idx & 15) << 2;
                float4 a = wk4[idx], b = wz4[idx];
                float4 at, bt;
                at.x = __uint_as_float(to_tf32(a.x));
                at.y = __uint_as_float(to_tf32(a.y));
                at.z = __uint_as_float(to_tf32(a.z));
                at.w = __uint_as_float(to_tf32(a.w));
                bt.x = __uint_as_float(to_tf32(b.x));
                bt.y = __uint_as_float(to_tf32(b.y));
                bt.z = __uint_as_float(to_tf32(b.z));
                bt.w = __uint_as_float(to_tf32(b.w));
                *(float4*)(wks + r * 68 + c) = at;
                *(float4*)(wzs + r * 68 + c) = bt;
            }
        }
        if (tid < 128) { bks[tid] = bxK[tid]; bzs[tid] = bxz[tid]; }
        __syncthreads();

        const int team = tid >> 7;          // 0..3
        const int wtid = tid & 127;
        const int tw   = wtid >> 5;
        const int lane = wtid & 31;
        const int g    = lane >> 2;
        const int tig  = lane & 3;
        float* xs = sm + XS_OFF + team * 4352;
        const int rA0 = 16 * tw + g, rA1 = rA0 + 8;
        float4* ogz = (float4*)g_gz;
        const int bar_id = 4 + team;

        // Tiles t-major: tau = chunk*256 + batch.
        for (int tau = (bx - SCAN_CTAS) * 4 + team; tau < 4096; tau += WORK_TEAMS) {
            const int ck = tau >> 8;        // chunk 0..15
            const int bb = tau & 255;       // batch
            const size_t row0 = (size_t)bb * TT + (size_t)ck * 64;

            // Stage x tile (64 x 64 -> 68-stride), 128 team threads.
            const float4* xg = (const float4*)(x + row0 * DD);
#pragma unroll
            for (int it = 0; it < 8; it++) {
                int idx = wtid + 128 * it;          // 1024 float4s
                int r = idx >> 4, c = (idx & 15) << 2;
                *(float4*)(xs + r * 68 + c) = xg[idx];
            }
            asm volatile("bar.sync %0, %1;" :: "r"(bar_id), "r"(128) : "memory");

            // A fragments (tf32-rn).
            uint32_t A[8][4];
#pragma unroll
            for (int kc = 0; kc < 8; kc++) {
                int cb = 8 * kc + tig;
                A[kc][0] = to_tf32(xs[rA0 * 68 + cb]);
                A[kc][1] = to_tf32(xs[rA1 * 68 + cb]);
                A[kc][2] = to_tf32(xs[rA0 * 68 + cb + 4]);
                A[kc][3] = to_tf32(xs[rA1 * 68 + cb + 4]);
            }
            const size_t o0 = (row0 + rA0) * 64;
            const size_t o1 = (row0 + rA1) * 64;

#pragma unroll 4
            for (int nt = 0; nt < 16; nt++) {
                const float* wkr = wks + (8 * nt + g) * 68 + tig;
                const float* wzr = wzs + (8 * nt + g) * 68 + tig;
                uint32_t BK0[8], BK1[8], BZ0[8], BZ1[8];
#pragma unroll
                for (int kc = 0; kc < 8; kc++) {
                    BK0[kc] = __float_as_uint(wkr[8 * kc]);
                    BK1[kc] = __float_as_uint(wkr[8 * kc + 4]);
                    BZ0[kc] = __float_as_uint(wzr[8 * kc]);
                    BZ1[kc] = __float_as_uint(wzr[8 * kc + 4]);
                }
                float cK[4] = {0, 0, 0, 0}, cz[4] = {0, 0, 0, 0};
#pragma unroll
                for (int kc = 0; kc < 8; kc++) {
                    mma4(cK[0], cK[1], cK[2], cK[3],
                         A[kc][0], A[kc][1], A[kc][2], A[kc][3], BK0[kc], BK1[kc]);
                    mma4(cz[0], cz[1], cz[2], cz[3],
                         A[kc][0], A[kc][1], A[kc][2], A[kc][3], BZ0[kc], BZ1[kc]);
                }
                const int h0 = 8 * nt + 2 * tig;
                const float bk0 = bks[h0], bk1 = bks[h0 + 1];
                const float bz0 = bzs[h0], bz1 = bzs[h0 + 1];

                float4 v0, v1;
                v0.x = cK[0] + bk0;  v0.y = tanh_hw(cz[0] + bz0);
                v0.z = cK[1] + bk1;  v0.w = tanh_hw(cz[1] + bz1);
                v1.x = cK[2] + bk0;  v1.y = tanh_hw(cz[2] + bz0);
                v1.z = cK[3] + bk1;  v1.w = tanh_hw(cz[3] + bz1);
                ogz[o0 + 4 * nt + tig] = v0;
                ogz[o1 + 4 * nt + tig] = v1;
            }

            // Publish: stores -> fence (every thread) -> team bar -> count.
            __threadfence();
            asm volatile("bar.sync %0, %1;" :: "r"(bar_id), "r"(128) : "memory");
            if (wtid == 0) atomicAdd(&g_done[ck], 1);
        }
        return;
    }

    // ================= SCAN CTA (r11 body, segmented with chunk polling) ====
    const int g    = tid >> 8;        // batch group 0..1
    const int u    = tid & 255;
    const int i    = u >> 1;          // output index 0..127
    const int half = u & 1;           // 64-input half
    const int b    = bx * GRP + g;

    ull w[32];
    {
        const ull* wr = (const ull*)(WhK + i * HH + half * 64);
#pragma unroll
        for (int m = 0; m < 32; m++) w[m] = wr[m];
    }
    const float bh = bhK[i];
    const int hidx = i + ((i & 64) >> 3);

    const float2* gp = g_gz + (size_t)b * TT * HH + i;
    float* op  = out + (size_t)b * TT * HH + i;
    float* op2 = op + BTH;

    float h = 0.0f;
    if (half == 0) hst[0][g][hidx] = 0.0f;

    // Wait for chunks 0 and 1 before the initial depth-3 prefetch.
    int have = 0;
    while (have < 2) {
        int d = *((volatile int*)&g_done[have]);
        if (d == 256) have++;
        else __nanosleep(200);
    }
    __threadfence();

    float2 gz0 = gp[0];
    float2 gz1 = gp[HH];
    float2 gz2 = gp[2 * HH];
    gp += 3 * HH;

    asm volatile("bar.sync %0, %1;" :: "r"(g + 1), "r"(256) : "memory");

    int cur = 0;
    for (int s = 0; s < 16; s++) {
        const int need = (s + 2 < NCHUNK) ? (s + 2) : NCHUNK;
        if (have < need) {
            while (have < need) {
                int d = *((volatile int*)&g_done[have]);
                if (d == 256) have++;
                else __nanosleep(200);
            }
            __threadfence();
        }
#pragma unroll 1
        for (int tt = 0; tt < 64; tt++) {
            // Half-dot: 16 LDS.128 (half starts at float offset 72*half).
            const ulonglong2* hv = (const ulonglong2*)(hst[cur][g] + 72 * half);
            ull a0 = 0, a1 = 0, a2 = 0, a3 = 0;
#pragma unroll
            for (int m = 0; m < 16; m += 2) {   // 16 ulonglong2 = 64 floats
                ulonglong2 hA = hv[m];
                ulonglong2 hB = hv[m + 1];
                fma2(a0, w[2 * m],     hA.x);
                fma2(a1, w[2 * m + 1], hA.y);
                fma2(a2, w[2 * m + 2], hB.x);
                fma2(a3, w[2 * m + 3], hB.y);
            }
            add2(a0, a2); add2(a1, a3); add2(a0, a1);
            float2 p = unpk(a0);
            float sv = p.x + p.y;
            sv += __shfl_xor_sync(0xFFFFFFFFu, sv, 1);   // combine halves
            sv += bh;

            float kg = sigmoid_hw(gz0.x + sv);
            h = tanh_hw(fmaf(kg, gz0.y - h, h));

            // rotate gate prefetch (depth 3; pad covers the tail)
            gz0 = gz1;
            gz1 = gz2;
            gz2 = *gp;
            gp += HH;

            if (half == 0) op[0] = h;
            else if (dup)  op2[0] = h;
            op += HH; op2 += HH;

            cur ^= 1;
            if (half == 0) hst[cur][g][hidx] = h;
            asm volatile("bar.sync %0, %1;" :: "r"(g + 1), "r"(256) : "memory");
        }
    }
}

// ---------------------------------------------------------------------------
extern "C" void kernel_launch(void* const* d_in, const int* in_sizes, int n_in,
                              void* d_out, int out_size)
{
    const float* x   = (const float*)d_in[0];
    const float* WxK = (const float*)d_in[1];
    const float* bxK = (const float*)d_in[2];
    const float* Wxz = (const float*)d_in[3];
    const float* bxz = (const float*)d_in[4];
    const float* WhK = (const float*)d_in[5];
    const float* bhK = (const float*)d_in[6];
    float* out = (float*)d_out;

    const int dyn_smem = DYN_FLOATS * (int)sizeof(float);   // ~137KB
    static int attr_set = 0;
    if (!attr_set) {
        cudaFuncSetAttribute(fused_kernel,
                             cudaFuncAttributeMaxDynamicSharedMemorySize,
                             dyn_smem);
        attr_set = 1;
    }

    const int dup = ((size_t)out_size >= 2 * BTH) ? 1 : 0;

    zero_done_kernel<<<1, 32>>>();
    fused_kernel<<<TOTAL_CTAS, 512, dyn_smem>>>(x, WxK, bxK, Wxz, bxz,
                                                WhK, bhK, out, dup);
}